// round 1
// baseline (speedup 1.0000x reference)
#include <cuda_runtime.h>

// Problem constants
#define BATCHSZ   2048
#define MDIM      512      // condensed QP size N*NU
#define NHOR      64
#define ITERS     100
#define STEPSZ    0.01f

// Kernel tiling
#define ROWS      16                    // batch rows per CTA
#define NCTAS     (BATCHSZ / ROWS)      // 128
#define NTHREADS  256
#define UPAD      18                    // padded row stride (floats) for u_s: avoids
                                        // update-phase bank conflicts, keeps 8B align

// --------- f32x2 helpers (FFMA2: full-rate fp32 on B300; 3-reg FFMA is half rate) ---
__device__ __forceinline__ unsigned long long splat2(float b) {
    unsigned long long r;
    asm("mov.b64 %0, {%1, %1};" : "=l"(r) : "f"(b));
    return r;
}
__device__ __forceinline__ void ffma2(unsigned long long& acc,
                                      unsigned long long a,
                                      unsigned long long b) {
    asm("fma.rn.f32x2 %0, %1, %2, %0;" : "+l"(acc) : "l"(a), "l"(b));
}
__device__ __forceinline__ void unpack2(unsigned long long v, float& lo, float& hi) {
    asm("mov.b64 {%0, %1}, %2;" : "=f"(lo), "=f"(hi) : "l"(v));
}

// -----------------------------------------------------------------------------------
// One CTA owns ROWS batch rows and runs all 100 PGD iterations locally.
//   grad[r,m] = sum_k H[m,k] * u[r,k]   (H symmetric -> load H[k,m], coalesced on m)
//   u <- clip(u - step*(grad + f), -1, 1)
// u kept in SMEM, layout u_s[k*UPAD + r] (k-major, rows contiguous -> LDS.64 row pairs,
// broadcast across all threads -> conflict-free).
// f kept in registers (each thread owns exactly its (m, r) entries).
// -----------------------------------------------------------------------------------
__global__ void __launch_bounds__(NTHREADS, 1)
mpc_pgd_kernel(const float* __restrict__ xref,   // [B, NHOR+1, 8]
               const float* __restrict__ H,      // [512, 512]
               const float* __restrict__ Phi,    // [NHOR+1, 8, 8]
               const float* __restrict__ Q,      // [8, 8]
               float* __restrict__ out)          // [B, 512]
{
    __shared__ __align__(16) float u_s[MDIM * UPAD];   // 512*18*4 = 36864 B

    const int t  = threadIdx.x;
    const int b0 = blockIdx.x * ROWS;
    const int m0 = t;            // first owned output column
    const int m1 = t + NTHREADS; // second owned output column (t + 256)

    // ---- init u = 0 ----
    for (int i = t; i < MDIM * UPAD; i += NTHREADS) u_s[i] = 0.0f;

    // ---- compute f for the thread's (m, r) entries into registers ----
    // f[b, kh*8+i] = -2 * sum_l (sum_j Phi[kh,i,j] Q[j,l]) * (xref[b,kh,l]-xref[b,0,l])
    float f_reg[2][ROWS];
    #pragma unroll
    for (int mi = 0; mi < 2; mi++) {
        const int m  = (mi == 0) ? m0 : m1;
        const int kh = m >> 3;
        const int ii = m & 7;
        float PQ[8];
        #pragma unroll
        for (int l = 0; l < 8; l++) {
            float s = 0.0f;
            #pragma unroll
            for (int j = 0; j < 8; j++)
                s += Phi[(kh * 8 + ii) * 8 + j] * Q[j * 8 + l];
            PQ[l] = s;
        }
        for (int r = 0; r < ROWS; r++) {
            const float* xr = xref + (size_t)(b0 + r) * (NHOR + 1) * 8;
            float s = 0.0f;
            #pragma unroll
            for (int l = 0; l < 8; l++)
                s += PQ[l] * (xr[kh * 8 + l] - xr[l]);
            f_reg[mi][r] = -2.0f * s;
        }
    }
    __syncthreads();

    // ---- 100 PGD iterations ----
    for (int it = 0; it < ITERS; it++) {
        // accumulators: 8 row-pairs per column, packed f32x2
        unsigned long long acc0[ROWS / 2], acc1[ROWS / 2];
        #pragma unroll
        for (int p = 0; p < ROWS / 2; p++) { acc0[p] = 0ull; acc1[p] = 0ull; }

        const float* __restrict__ Hc0 = H + m0;
        const float* __restrict__ Hc1 = H + m1;

        #pragma unroll 4
        for (int k = 0; k < MDIM; k++) {
            const float h0 = Hc0[k * MDIM];       // H[k, m0]  (coalesced on t)
            const float h1 = Hc1[k * MDIM];       // H[k, m1]
            const unsigned long long h0p = splat2(h0);
            const unsigned long long h1p = splat2(h1);
            const unsigned long long* up =
                reinterpret_cast<const unsigned long long*>(&u_s[k * UPAD]);
            #pragma unroll
            for (int p = 0; p < ROWS / 2; p++) {
                const unsigned long long u2 = up[p];   // broadcast LDS.64
                ffma2(acc0[p], u2, h0p);
                ffma2(acc1[p], u2, h1p);
            }
        }
        __syncthreads();   // all reads of u done

        // update: u <- clip(u - step*(grad + f))
        #pragma unroll
        for (int p = 0; p < ROWS / 2; p++) {
            float g0lo, g0hi, g1lo, g1hi;
            unpack2(acc0[p], g0lo, g0hi);
            unpack2(acc1[p], g1lo, g1hi);
            const int r0 = 2 * p, r1 = 2 * p + 1;

            float u00 = u_s[m0 * UPAD + r0];
            float u01 = u_s[m0 * UPAD + r1];
            float u10 = u_s[m1 * UPAD + r0];
            float u11 = u_s[m1 * UPAD + r1];

            u00 = fminf(fmaxf(u00 - STEPSZ * (g0lo + f_reg[0][r0]), -1.0f), 1.0f);
            u01 = fminf(fmaxf(u01 - STEPSZ * (g0hi + f_reg[0][r1]), -1.0f), 1.0f);
            u10 = fminf(fmaxf(u10 - STEPSZ * (g1lo + f_reg[1][r0]), -1.0f), 1.0f);
            u11 = fminf(fmaxf(u11 - STEPSZ * (g1hi + f_reg[1][r1]), -1.0f), 1.0f);

            u_s[m0 * UPAD + r0] = u00;
            u_s[m0 * UPAD + r1] = u01;
            u_s[m1 * UPAD + r0] = u10;
            u_s[m1 * UPAD + r1] = u11;
        }
        __syncthreads();   // updates visible before next GEMM
    }

    // ---- write result: out[b, m] ----
    #pragma unroll
    for (int r = 0; r < ROWS; r++) {
        out[(size_t)(b0 + r) * MDIM + m0] = u_s[m0 * UPAD + r];
        out[(size_t)(b0 + r) * MDIM + m1] = u_s[m1 * UPAD + r];
    }
}

extern "C" void kernel_launch(void* const* d_in, const int* in_sizes, int n_in,
                              void* d_out, int out_size) {
    // metadata order: x0, xref, H, Phi, Q   (x0 unused by the reference math)
    const float* xref = (const float*)d_in[1];
    const float* H    = (const float*)d_in[2];
    const float* Phi  = (const float*)d_in[3];
    const float* Q    = (const float*)d_in[4];
    float* out        = (float*)d_out;

    mpc_pgd_kernel<<<NCTAS, NTHREADS>>>(xref, H, Phi, Q, out);
}